// round 6
// baseline (speedup 1.0000x reference)
#include <cuda_runtime.h>
#include <cuda_bf16.h>
#include <cstdint>

// Problem constants (fixed by reference setup_inputs): 40000 nodes, E=640000.
#define NN 40000
#define FF 128
#define CC 40
#define EE 640000

__device__ float g_deg[NN];
__device__ float g_buf0[NN * FF];
__device__ float g_buf1[NN * FF];
__device__ int   g_is64;

// ---------------------------------------------------------------------------
// Edge dtype detection: int64 little-endian, idx < 2^31 => odd 32-bit words 0.
// ---------------------------------------------------------------------------
__global__ void k_detect(const int* __restrict__ ei) {
    int lane = threadIdx.x;
    int nz = 0;
    for (int i = lane; i < 512; i += 32) nz |= (ei[2 * i + 1] != 0);
    unsigned any = __ballot_sync(0xFFFFFFFFu, nz);
    if (lane == 0) g_is64 = (any == 0u);
}

__device__ __forceinline__ int edge_idx(const int* ei, int pos) {
    if (g_is64) return (int)((const long long*)ei)[pos];
    return ei[pos];
}

// ---------------------------------------------------------------------------
// Degrees
// ---------------------------------------------------------------------------
__global__ void k_deg_init() {
    int i = blockIdx.x * blockDim.x + threadIdx.x;
    if (i < NN) g_deg[i] = 1.0f;                 // self loop
}

__global__ void k_deg_acc(const int* __restrict__ ei) {
    int i = blockIdx.x * blockDim.x + threadIdx.x;
    if (i < EE) atomicAdd(&g_deg[edge_idx(ei, EE + i)], 1.0f);   // dst row
}

__global__ void k_dinv() {
    int i = blockIdx.x * blockDim.x + threadIdx.x;
    if (i < NN) g_deg[i] = rsqrtf(g_deg[i]);
}

// ---------------------------------------------------------------------------
// Naive self-loop: Y[n][f] = X[n][f] * dinv[n]^2   (thread per element)
// ---------------------------------------------------------------------------
__global__ void k_scale_naive(const float* __restrict__ X, float* __restrict__ Y) {
    int i = blockIdx.x * blockDim.x + threadIdx.x;
    if (i >= NN * FF) return;
    int n = i / FF;
    float d = g_deg[n];
    Y[i] = X[i] * d * d;
}

// ---------------------------------------------------------------------------
// Naive SpMM: block = edge, thread = feature. Y[dst][f] += X[src][f]*nrm.
// ---------------------------------------------------------------------------
__global__ void k_spmm_naive(const int* __restrict__ ei,
                             const float* __restrict__ X,
                             float* __restrict__ Y) {
    int e = blockIdx.x;
    int f = threadIdx.x;
    int s = edge_idx(ei, e);
    int d = edge_idx(ei, EE + e);
    float nrm = g_deg[s] * g_deg[d];
    atomicAdd(&Y[d * FF + f], X[s * FF + f] * nrm);
}

// ---------------------------------------------------------------------------
// Naive GEMM+ReLU: block = row (128 threads), thread = out feature.
// Y[r][f] = relu(sum_k X[r][k] * W[f][k] + b[f])
// ---------------------------------------------------------------------------
__global__ void k_gemm_naive(const float* __restrict__ X,
                             const float* __restrict__ W,
                             const float* __restrict__ b,
                             float* __restrict__ Y) {
    int r = blockIdx.x;
    int f = threadIdx.x;
    float acc = b[f];
    const float* xr = X + r * FF;
    const float* wf = W + f * FF;
    for (int k = 0; k < FF; k++) acc += xr[k] * wf[k];
    Y[r * FF + f] = fmaxf(acc, 0.0f);
}

// ---------------------------------------------------------------------------
// Naive head: block = row (64 threads), thread = class (<40).
// out[r][c] = sum_k X[r][k] * Wl[c][k] + bl[c]
// ---------------------------------------------------------------------------
__global__ void k_head_naive(const float* __restrict__ X,
                             const float* __restrict__ W,
                             const float* __restrict__ b,
                             float* __restrict__ Y) {
    int r = blockIdx.x;
    int c = threadIdx.x;
    if (c >= CC) return;
    float acc = b[c];
    const float* xr = X + r * FF;
    const float* wc = W + c * FF;
    for (int k = 0; k < FF; k++) acc += xr[k] * wc[k];
    Y[r * CC + c] = acc;
}

// ---------------------------------------------------------------------------
// Launch
// ---------------------------------------------------------------------------
extern "C" void kernel_launch(void* const* d_in, const int* in_sizes, int n_in,
                              void* d_out, int out_size) {
    const float* x   = (const float*)d_in[0];
    const int*   ei  = (const int*)d_in[1];
    const float* W1  = (const float*)d_in[2];
    const float* b1  = (const float*)d_in[3];
    const float* W2  = (const float*)d_in[4];
    const float* b2  = (const float*)d_in[5];
    const float* Wl  = (const float*)d_in[6];
    const float* bl  = (const float*)d_in[7];
    float*       out = (float*)d_out;

    float* buf0; cudaGetSymbolAddress((void**)&buf0, g_buf0);
    float* buf1; cudaGetSymbolAddress((void**)&buf1, g_buf1);

    k_detect<<<1, 32>>>(ei);

    k_deg_init<<<(NN + 255) / 256, 256>>>();
    k_deg_acc<<<(EE + 255) / 256, 256>>>(ei);
    k_dinv<<<(NN + 255) / 256, 256>>>();

    // layer 1
    k_scale_naive<<<(NN * FF + 255) / 256, 256>>>(x, buf0);
    k_spmm_naive<<<EE, FF>>>(ei, x, buf0);
    k_gemm_naive<<<NN, FF>>>(buf0, W1, b1, buf1);

    // layer 2
    k_scale_naive<<<(NN * FF + 255) / 256, 256>>>(buf1, buf0);
    k_spmm_naive<<<EE, FF>>>(ei, buf1, buf0);
    k_gemm_naive<<<NN, FF>>>(buf0, W2, b2, buf1);

    // head
    k_head_naive<<<NN, 64>>>(buf1, Wl, bl, out);
}

// round 7
// speedup vs baseline: 1.0931x; 1.0931x over previous
#include <cuda_runtime.h>
#include <cuda_bf16.h>
#include <cstdint>

// Problem constants (fixed by reference setup_inputs): 40000 nodes, E=640000.
#define NN 40000
#define FF 128
#define CC 40
#define EE 640000

__device__ float g_deg[NN];
__device__ float g_buf0[NN * FF];
__device__ float g_buf1[NN * FF];
__device__ int   g_is64;

// ---------------------------------------------------------------------------
// Edge dtype detection: int64 little-endian, idx < 2^31 => odd 32-bit words 0.
// ---------------------------------------------------------------------------
__global__ void k_detect(const int* __restrict__ ei) {
    int lane = threadIdx.x;
    int nz = 0;
    for (int i = lane; i < 512; i += 32) nz |= (ei[2 * i + 1] != 0);
    unsigned any = __ballot_sync(0xFFFFFFFFu, nz);
    if (lane == 0) g_is64 = (any == 0u);
}

__device__ __forceinline__ int edge_idx(const int* ei, int pos) {
    if (g_is64) return (int)((const long long*)ei)[pos];
    return ei[pos];
}

// ---------------------------------------------------------------------------
// Degrees
// ---------------------------------------------------------------------------
__global__ void k_deg_init() {
    int i = blockIdx.x * blockDim.x + threadIdx.x;
    if (i < NN) g_deg[i] = 1.0f;                 // self loop
}

__global__ void k_deg_acc(const int* __restrict__ ei) {
    int i = blockIdx.x * blockDim.x + threadIdx.x;
    if (i < EE) atomicAdd(&g_deg[edge_idx(ei, EE + i)], 1.0f);   // dst row
}

__global__ void k_dinv() {
    int i = blockIdx.x * blockDim.x + threadIdx.x;
    if (i < NN) g_deg[i] = rsqrtf(g_deg[i]);
}

// ---------------------------------------------------------------------------
// Self-loop (float4): Y[n][f] = X[n][f] * dinv[n]^2.  t indexes float4 chunks.
// ---------------------------------------------------------------------------
__global__ void k_scale2(const float* __restrict__ X, float* __restrict__ Y) {
    int t = blockIdx.x * blockDim.x + threadIdx.x;   // 0 .. NN*32-1
    if (t >= NN * (FF / 4)) return;
    int n = t >> 5;                                   // chunk 32 float4s per row
    float d = g_deg[n];
    float s = d * d;
    float4 v = ((const float4*)X)[t];
    v.x *= s; v.y *= s; v.z *= s; v.w *= s;
    ((float4*)Y)[t] = v;
}

// ---------------------------------------------------------------------------
// Edge SpMM (optimized, fresh): flat thread space over (edge, chunk) pairs.
// Thread t: edge e = t>>5, chunk c = t&31 (float4 = 4 floats; 32 chunks/row).
// Gather X[s] row chunk, scale, scatter with red.global.add.v4.f32
// (proven equivalent to 4x atomicAdd by R3==R4 bit-identical results).
// ---------------------------------------------------------------------------
__global__ void k_spmm2(const int* __restrict__ ei,
                        const float* __restrict__ X,
                        float* __restrict__ Y) {
    int t = blockIdx.x * blockDim.x + threadIdx.x;   // 0 .. EE*32-1
    if (t >= EE * 32) return;
    int e = t >> 5;
    int c = t & 31;
    int s = edge_idx(ei, e);
    int d = edge_idx(ei, EE + e);
    float nrm = g_deg[s] * g_deg[d];
    float4 v = ((const float4*)(X + (size_t)s * FF))[c];
    float* p = Y + (size_t)d * FF + c * 4;
    asm volatile("red.global.add.v4.f32 [%0], {%1,%2,%3,%4};"
                 :: "l"(p), "f"(v.x * nrm), "f"(v.y * nrm),
                    "f"(v.z * nrm), "f"(v.w * nrm)
                 : "memory");
}

// ---------------------------------------------------------------------------
// Naive GEMM+ReLU (known good from R6): block = row, thread = out feature.
// ---------------------------------------------------------------------------
__global__ void k_gemm_naive(const float* __restrict__ X,
                             const float* __restrict__ W,
                             const float* __restrict__ b,
                             float* __restrict__ Y) {
    int r = blockIdx.x;
    int f = threadIdx.x;
    float acc = b[f];
    const float* xr = X + r * FF;
    const float* wf = W + f * FF;
    for (int k = 0; k < FF; k++) acc += xr[k] * wf[k];
    Y[r * FF + f] = fmaxf(acc, 0.0f);
}

// ---------------------------------------------------------------------------
// Naive head (known good from R6): block = row, thread = class.
// ---------------------------------------------------------------------------
__global__ void k_head_naive(const float* __restrict__ X,
                             const float* __restrict__ W,
                             const float* __restrict__ b,
                             float* __restrict__ Y) {
    int r = blockIdx.x;
    int c = threadIdx.x;
    if (c >= CC) return;
    float acc = b[c];
    const float* xr = X + r * FF;
    const float* wc = W + c * FF;
    for (int k = 0; k < FF; k++) acc += xr[k] * wc[k];
    Y[r * CC + c] = acc;
}

// ---------------------------------------------------------------------------
// Launch
// ---------------------------------------------------------------------------
extern "C" void kernel_launch(void* const* d_in, const int* in_sizes, int n_in,
                              void* d_out, int out_size) {
    const float* x   = (const float*)d_in[0];
    const int*   ei  = (const int*)d_in[1];
    const float* W1  = (const float*)d_in[2];
    const float* b1  = (const float*)d_in[3];
    const float* W2  = (const float*)d_in[4];
    const float* b2  = (const float*)d_in[5];
    const float* Wl  = (const float*)d_in[6];
    const float* bl  = (const float*)d_in[7];
    float*       out = (float*)d_out;

    float* buf0; cudaGetSymbolAddress((void**)&buf0, g_buf0);
    float* buf1; cudaGetSymbolAddress((void**)&buf1, g_buf1);

    k_detect<<<1, 32>>>(ei);

    k_deg_init<<<(NN + 255) / 256, 256>>>();
    k_deg_acc<<<(EE + 255) / 256, 256>>>(ei);
    k_dinv<<<(NN + 255) / 256, 256>>>();

    const int spmm_threads = EE * 32;           // 20.48M
    const int scale_threads = NN * (FF / 4);    // 1.28M

    // layer 1
    k_scale2<<<(scale_threads + 255) / 256, 256>>>(x, buf0);
    k_spmm2<<<(spmm_threads + 255) / 256, 256>>>(ei, x, buf0);
    k_gemm_naive<<<NN, FF>>>(buf0, W1, b1, buf1);

    // layer 2
    k_scale2<<<(scale_threads + 255) / 256, 256>>>(buf1, buf0);
    k_spmm2<<<(spmm_threads + 255) / 256, 256>>>(ei, buf1, buf0);
    k_gemm_naive<<<NN, FF>>>(buf0, W2, b2, buf1);

    // head
    k_head_naive<<<NN, 64>>>(buf1, Wl, bl, out);
}

// round 8
// speedup vs baseline: 6.0070x; 5.4953x over previous
#include <cuda_runtime.h>
#include <cuda_bf16.h>
#include <cstdint>

// Problem constants (fixed by reference setup_inputs): 40000 nodes, E=640000.
#define NN 40000
#define FF 128
#define CC 40
#define EE 640000

__device__ float g_deg[NN];
__device__ float g_buf0[NN * FF];
__device__ float g_buf1[NN * FF];
__device__ int   g_is64;

// ---------------------------------------------------------------------------
// Edge dtype detection: int64 little-endian, idx < 2^31 => odd 32-bit words 0.
// ---------------------------------------------------------------------------
__global__ void k_detect(const int* __restrict__ ei) {
    int lane = threadIdx.x;
    int nz = 0;
    for (int i = lane; i < 512; i += 32) nz |= (ei[2 * i + 1] != 0);
    unsigned any = __ballot_sync(0xFFFFFFFFu, nz);
    if (lane == 0) g_is64 = (any == 0u);
}

__device__ __forceinline__ int edge_idx(const int* ei, int pos) {
    if (g_is64) return (int)((const long long*)ei)[pos];
    return ei[pos];
}

// ---------------------------------------------------------------------------
// Degrees
// ---------------------------------------------------------------------------
__global__ void k_deg_init() {
    int i = blockIdx.x * blockDim.x + threadIdx.x;
    if (i < NN) g_deg[i] = 1.0f;                 // self loop
}

__global__ void k_deg_acc(const int* __restrict__ ei) {
    int i = blockIdx.x * blockDim.x + threadIdx.x;
    if (i < EE) atomicAdd(&g_deg[edge_idx(ei, EE + i)], 1.0f);   // dst row
}

__global__ void k_dinv() {
    int i = blockIdx.x * blockDim.x + threadIdx.x;
    if (i < NN) g_deg[i] = rsqrtf(g_deg[i]);
}

// ---------------------------------------------------------------------------
// Self-loop (float4, validated R7): Y[n][f] = X[n][f] * dinv[n]^2.
// ---------------------------------------------------------------------------
__global__ void k_scale2(const float* __restrict__ X, float* __restrict__ Y) {
    int t = blockIdx.x * blockDim.x + threadIdx.x;   // 0 .. NN*32-1
    if (t >= NN * (FF / 4)) return;
    int n = t >> 5;
    float d = g_deg[n];
    float s = d * d;
    float4 v = ((const float4*)X)[t];
    v.x *= s; v.y *= s; v.z *= s; v.w *= s;
    ((float4*)Y)[t] = v;
}

// ---------------------------------------------------------------------------
// Edge SpMM (validated R7): thread per (edge, float4-chunk), red.v4 scatter.
// ---------------------------------------------------------------------------
__global__ void k_spmm2(const int* __restrict__ ei,
                        const float* __restrict__ X,
                        float* __restrict__ Y) {
    int t = blockIdx.x * blockDim.x + threadIdx.x;   // 0 .. EE*32-1
    if (t >= EE * 32) return;
    int e = t >> 5;
    int c = t & 31;
    int s = edge_idx(ei, e);
    int d = edge_idx(ei, EE + e);
    float nrm = g_deg[s] * g_deg[d];
    float4 v = ((const float4*)(X + (size_t)s * FF))[c];
    float* p = Y + (size_t)d * FF + c * 4;
    asm volatile("red.global.add.v4.f32 [%0], {%1,%2,%3,%4};"
                 :: "l"(p), "f"(v.x * nrm), "f"(v.y * nrm),
                    "f"(v.z * nrm), "f"(v.w * nrm)
                 : "memory");
}

// ---------------------------------------------------------------------------
// Tiled GEMM+ReLU (fresh derivation): Y = relu(X @ W^T + b).
// X: (M,128), W: (128,128) row-major W[f][k].  Grid NN/64, block 256.
// Block tile: 64 rows x 128 cols.  Thread (ty=tid>>5, tx=tid&31):
//   rows ty*8..ty*8+7, cols tx*4..tx*4+3  -> 8x4 micro-tile.
// k staged in 32-wide slices: xs[r][k] (pad 33), ws[k][f] (pad 132; 132*4
// bytes is 16B-aligned and row stride of 4 banks kills transpose conflicts).
// ---------------------------------------------------------------------------
__global__ void k_gemm3(const float* __restrict__ X,
                        const float* __restrict__ W,
                        const float* __restrict__ b,
                        float* __restrict__ Y) {
    __shared__ float xs[64][33];
    __shared__ float ws[32][132];

    int tid = threadIdx.x;
    int tx = tid & 31;
    int ty = tid >> 5;
    int row0 = blockIdx.x * 64;

    float acc[8][4];
#pragma unroll
    for (int i = 0; i < 8; i++)
#pragma unroll
        for (int j = 0; j < 4; j++) acc[i][j] = 0.0f;

    for (int kb = 0; kb < FF; kb += 32) {
        if (kb) __syncthreads();   // drain previous slice's readers
        // stage X tile: 64 rows x 32 k  (512 float4s, 2 per thread)
#pragma unroll
        for (int u = tid; u < 512; u += 256) {
            int r = u >> 3;
            int c4 = (u & 7) * 4;
            float4 v = *(const float4*)&X[(row0 + r) * FF + kb + c4];
            xs[r][c4 + 0] = v.x; xs[r][c4 + 1] = v.y;
            xs[r][c4 + 2] = v.z; xs[r][c4 + 3] = v.w;
        }
        // stage W tile transposed: ws[k][f] = W[f][kb+k]  (1024 float4s)
#pragma unroll
        for (int u = tid; u < 1024; u += 256) {
            int f = u >> 3;
            int c4 = (u & 7) * 4;
            float4 v = *(const float4*)&W[f * FF + kb + c4];
            ws[c4 + 0][f] = v.x; ws[c4 + 1][f] = v.y;
            ws[c4 + 2][f] = v.z; ws[c4 + 3][f] = v.w;
        }
        __syncthreads();

#pragma unroll
        for (int k = 0; k < 32; k++) {
            float4 wv = *(const float4*)&ws[k][tx * 4];
            float xv[8];
#pragma unroll
            for (int i = 0; i < 8; i++) xv[i] = xs[ty * 8 + i][k];
#pragma unroll
            for (int i = 0; i < 8; i++) {
                acc[i][0] = fmaf(xv[i], wv.x, acc[i][0]);
                acc[i][1] = fmaf(xv[i], wv.y, acc[i][1]);
                acc[i][2] = fmaf(xv[i], wv.z, acc[i][2]);
                acc[i][3] = fmaf(xv[i], wv.w, acc[i][3]);
            }
        }
    }

    float4 bv = *(const float4*)&b[tx * 4];
#pragma unroll
    for (int i = 0; i < 8; i++) {
        int r = row0 + ty * 8 + i;
        float4 o;
        o.x = fmaxf(acc[i][0] + bv.x, 0.0f);
        o.y = fmaxf(acc[i][1] + bv.y, 0.0f);
        o.z = fmaxf(acc[i][2] + bv.z, 0.0f);
        o.w = fmaxf(acc[i][3] + bv.w, 0.0f);
        *(float4*)&Y[r * FF + tx * 4] = o;
    }
}

// ---------------------------------------------------------------------------
// Naive head (validated R6): block = row, thread = class. W L1-resident.
// ---------------------------------------------------------------------------
__global__ void k_head_naive(const float* __restrict__ X,
                             const float* __restrict__ W,
                             const float* __restrict__ b,
                             float* __restrict__ Y) {
    int r = blockIdx.x;
    int c = threadIdx.x;
    if (c >= CC) return;
    float acc = b[c];
    const float* xr = X + r * FF;
    const float* wc = W + c * FF;
    for (int k = 0; k < FF; k++) acc += xr[k] * wc[k];
    Y[r * CC + c] = acc;
}

// ---------------------------------------------------------------------------
// Launch
// ---------------------------------------------------------------------------
extern "C" void kernel_launch(void* const* d_in, const int* in_sizes, int n_in,
                              void* d_out, int out_size) {
    const float* x   = (const float*)d_in[0];
    const int*   ei  = (const int*)d_in[1];
    const float* W1  = (const float*)d_in[2];
    const float* b1  = (const float*)d_in[3];
    const float* W2  = (const float*)d_in[4];
    const float* b2  = (const float*)d_in[5];
    const float* Wl  = (const float*)d_in[6];
    const float* bl  = (const float*)d_in[7];
    float*       out = (float*)d_out;

    float* buf0; cudaGetSymbolAddress((void**)&buf0, g_buf0);
    float* buf1; cudaGetSymbolAddress((void**)&buf1, g_buf1);

    k_detect<<<1, 32>>>(ei);

    k_deg_init<<<(NN + 255) / 256, 256>>>();
    k_deg_acc<<<(EE + 255) / 256, 256>>>(ei);
    k_dinv<<<(NN + 255) / 256, 256>>>();

    const int spmm_threads = EE * 32;           // 20.48M
    const int scale_threads = NN * (FF / 4);    // 1.28M

    // layer 1
    k_scale2<<<(scale_threads + 255) / 256, 256>>>(x, buf0);
    k_spmm2<<<(spmm_threads + 255) / 256, 256>>>(ei, x, buf0);
    k_gemm3<<<NN / 64, 256>>>(buf0, W1, b1, buf1);

    // layer 2
    k_scale2<<<(scale_threads + 255) / 256, 256>>>(buf1, buf0);
    k_spmm2<<<(spmm_threads + 255) / 256, 256>>>(ei, buf1, buf0);
    k_gemm3<<<NN / 64, 256>>>(buf0, W2, b2, buf1);

    // head
    k_head_naive<<<NN, 64>>>(buf1, Wl, bl, out);
}

// round 9
// speedup vs baseline: 6.2403x; 1.0388x over previous
#include <cuda_runtime.h>
#include <cuda_bf16.h>
#include <cstdint>

// Problem constants (fixed by reference setup_inputs): 40000 nodes, E=640000.
#define NN 40000
#define FF 128
#define CC 40
#define EE 640000

__device__ float g_deg[NN];          // dinv values
__device__ int   g_cnt[NN];          // in-degree (edges only)
__device__ int   g_off[NN];          // CSR row starts (by dst)
__device__ int   g_cur[NN];          // fill cursors
__device__ int   g_csr_src[EE];      // src node per CSR slot
__device__ float g_buf0[NN * FF];
__device__ float g_buf1[NN * FF];
__device__ int   g_is64;

// ---------------------------------------------------------------------------
// Edge dtype detection: int64 little-endian, idx < 2^31 => odd 32-bit words 0.
// ---------------------------------------------------------------------------
__global__ void k_detect(const int* __restrict__ ei) {
    int lane = threadIdx.x;
    int nz = 0;
    for (int i = lane; i < 512; i += 32) nz |= (ei[2 * i + 1] != 0);
    unsigned any = __ballot_sync(0xFFFFFFFFu, nz);
    if (lane == 0) g_is64 = (any == 0u);
}

__device__ __forceinline__ int edge_idx(const int* ei, int pos) {
    if (g_is64) return (int)((const long long*)ei)[pos];
    return ei[pos];
}

// ---------------------------------------------------------------------------
// CSR build
// ---------------------------------------------------------------------------
__global__ void k_cnt_zero() {
    int i = blockIdx.x * blockDim.x + threadIdx.x;
    if (i < NN) g_cnt[i] = 0;
}

__global__ void k_cnt_acc(const int* __restrict__ ei) {
    int i = blockIdx.x * blockDim.x + threadIdx.x;
    if (i < EE) atomicAdd(&g_cnt[edge_idx(ei, EE + i)], 1);   // dst row
}

__global__ void k_dinv() {
    int i = blockIdx.x * blockDim.x + threadIdx.x;
    if (i < NN) g_deg[i] = rsqrtf((float)(g_cnt[i] + 1));     // +1 self loop
}

// Single-block exclusive scan of g_cnt -> g_off (and g_cur copy).
__global__ void k_scan() {
    __shared__ int sh[1024];
    __shared__ int carry;
    int tid = threadIdx.x;
    if (tid == 0) carry = 0;
    __syncthreads();
    for (int base = 0; base < NN; base += 1024) {
        int i = base + tid;
        int v = (i < NN) ? g_cnt[i] : 0;
        sh[tid] = v;
        __syncthreads();
#pragma unroll
        for (int s = 1; s < 1024; s <<= 1) {
            int t = (tid >= s) ? sh[tid - s] : 0;
            __syncthreads();
            sh[tid] += t;
            __syncthreads();
        }
        int excl = sh[tid] - v + carry;
        if (i < NN) { g_off[i] = excl; g_cur[i] = excl; }
        __syncthreads();
        if (tid == 0) carry += sh[1023];
        __syncthreads();
    }
}

__global__ void k_fill(const int* __restrict__ ei) {
    int e = blockIdx.x * blockDim.x + threadIdx.x;
    if (e >= EE) return;
    int s = edge_idx(ei, e);
    int d = edge_idx(ei, EE + e);
    int pos = atomicAdd(&g_cur[d], 1);
    g_csr_src[pos] = s;
}

// ---------------------------------------------------------------------------
// CSR SpMM with fused self-loop: one warp per dst row, lane = float4 chunk.
// Y[d] = X[d]*dinv[d]^2 + sum_{s in N(d)} X[s]*dinv[s]*dinv[d]
// ---------------------------------------------------------------------------
__global__ void k_spmm_csr(const float* __restrict__ X, float* __restrict__ Y) {
    int w = blockIdx.x * 8 + (threadIdx.x >> 5);   // dst node
    if (w >= NN) return;
    int lane = threadIdx.x & 31;

    float dd = g_deg[w];
    float4 acc = ((const float4*)(X + (size_t)w * FF))[lane];
    float sl = dd * dd;
    acc.x *= sl; acc.y *= sl; acc.z *= sl; acc.w *= sl;

    int beg = g_off[w];
    int end = beg + g_cnt[w];
    int j = beg;
    // 2-way unroll for memory-level parallelism
    for (; j + 1 < end; j += 2) {
        int s0 = __ldg(&g_csr_src[j]);
        int s1 = __ldg(&g_csr_src[j + 1]);
        float n0 = __ldg(&g_deg[s0]) * dd;
        float n1 = __ldg(&g_deg[s1]) * dd;
        float4 v0 = ((const float4*)(X + (size_t)s0 * FF))[lane];
        float4 v1 = ((const float4*)(X + (size_t)s1 * FF))[lane];
        acc.x = fmaf(v0.x, n0, acc.x); acc.y = fmaf(v0.y, n0, acc.y);
        acc.z = fmaf(v0.z, n0, acc.z); acc.w = fmaf(v0.w, n0, acc.w);
        acc.x = fmaf(v1.x, n1, acc.x); acc.y = fmaf(v1.y, n1, acc.y);
        acc.z = fmaf(v1.z, n1, acc.z); acc.w = fmaf(v1.w, n1, acc.w);
    }
    if (j < end) {
        int s0 = __ldg(&g_csr_src[j]);
        float n0 = __ldg(&g_deg[s0]) * dd;
        float4 v0 = ((const float4*)(X + (size_t)s0 * FF))[lane];
        acc.x = fmaf(v0.x, n0, acc.x); acc.y = fmaf(v0.y, n0, acc.y);
        acc.z = fmaf(v0.z, n0, acc.z); acc.w = fmaf(v0.w, n0, acc.w);
    }

    ((float4*)(Y + (size_t)w * FF))[lane] = acc;
}

// ---------------------------------------------------------------------------
// Tiled GEMM+ReLU (validated R8): Y = relu(X @ W^T + b).
// ---------------------------------------------------------------------------
__global__ void k_gemm3(const float* __restrict__ X,
                        const float* __restrict__ W,
                        const float* __restrict__ b,
                        float* __restrict__ Y) {
    __shared__ float xs[64][33];
    __shared__ float ws[32][132];

    int tid = threadIdx.x;
    int tx = tid & 31;
    int ty = tid >> 5;
    int row0 = blockIdx.x * 64;

    float acc[8][4];
#pragma unroll
    for (int i = 0; i < 8; i++)
#pragma unroll
        for (int j = 0; j < 4; j++) acc[i][j] = 0.0f;

    for (int kb = 0; kb < FF; kb += 32) {
        if (kb) __syncthreads();
#pragma unroll
        for (int u = tid; u < 512; u += 256) {
            int r = u >> 3;
            int c4 = (u & 7) * 4;
            float4 v = *(const float4*)&X[(row0 + r) * FF + kb + c4];
            xs[r][c4 + 0] = v.x; xs[r][c4 + 1] = v.y;
            xs[r][c4 + 2] = v.z; xs[r][c4 + 3] = v.w;
        }
#pragma unroll
        for (int u = tid; u < 1024; u += 256) {
            int f = u >> 3;
            int c4 = (u & 7) * 4;
            float4 v = *(const float4*)&W[f * FF + kb + c4];
            ws[c4 + 0][f] = v.x; ws[c4 + 1][f] = v.y;
            ws[c4 + 2][f] = v.z; ws[c4 + 3][f] = v.w;
        }
        __syncthreads();

#pragma unroll
        for (int k = 0; k < 32; k++) {
            float4 wv = *(const float4*)&ws[k][tx * 4];
            float xv[8];
#pragma unroll
            for (int i = 0; i < 8; i++) xv[i] = xs[ty * 8 + i][k];
#pragma unroll
            for (int i = 0; i < 8; i++) {
                acc[i][0] = fmaf(xv[i], wv.x, acc[i][0]);
                acc[i][1] = fmaf(xv[i], wv.y, acc[i][1]);
                acc[i][2] = fmaf(xv[i], wv.z, acc[i][2]);
                acc[i][3] = fmaf(xv[i], wv.w, acc[i][3]);
            }
        }
    }

    float4 bv = *(const float4*)&b[tx * 4];
#pragma unroll
    for (int i = 0; i < 8; i++) {
        int r = row0 + ty * 8 + i;
        float4 o;
        o.x = fmaxf(acc[i][0] + bv.x, 0.0f);
        o.y = fmaxf(acc[i][1] + bv.y, 0.0f);
        o.z = fmaxf(acc[i][2] + bv.z, 0.0f);
        o.w = fmaxf(acc[i][3] + bv.w, 0.0f);
        *(float4*)&Y[r * FF + tx * 4] = o;
    }
}

// ---------------------------------------------------------------------------
// Naive head (validated R6): block = row, thread = class. W L1-resident.
// ---------------------------------------------------------------------------
__global__ void k_head_naive(const float* __restrict__ X,
                             const float* __restrict__ W,
                             const float* __restrict__ b,
                             float* __restrict__ Y) {
    int r = blockIdx.x;
    int c = threadIdx.x;
    if (c >= CC) return;
    float acc = b[c];
    const float* xr = X + r * FF;
    const float* wc = W + c * FF;
    for (int k = 0; k < FF; k++) acc += xr[k] * wc[k];
    Y[r * CC + c] = acc;
}

// ---------------------------------------------------------------------------
// Launch
// ---------------------------------------------------------------------------
extern "C" void kernel_launch(void* const* d_in, const int* in_sizes, int n_in,
                              void* d_out, int out_size) {
    const float* x   = (const float*)d_in[0];
    const int*   ei  = (const int*)d_in[1];
    const float* W1  = (const float*)d_in[2];
    const float* b1  = (const float*)d_in[3];
    const float* W2  = (const float*)d_in[4];
    const float* b2  = (const float*)d_in[5];
    const float* Wl  = (const float*)d_in[6];
    const float* bl  = (const float*)d_in[7];
    float*       out = (float*)d_out;

    float* buf0; cudaGetSymbolAddress((void**)&buf0, g_buf0);
    float* buf1; cudaGetSymbolAddress((void**)&buf1, g_buf1);

    k_detect<<<1, 32>>>(ei);

    // CSR build (by dst) + dinv
    k_cnt_zero<<<(NN + 255) / 256, 256>>>();
    k_cnt_acc<<<(EE + 255) / 256, 256>>>(ei);
    k_dinv<<<(NN + 255) / 256, 256>>>();
    k_scan<<<1, 1024>>>();
    k_fill<<<(EE + 255) / 256, 256>>>(ei);

    // layer 1
    k_spmm_csr<<<(NN + 7) / 8, 256>>>(x, buf0);
    k_gemm3<<<NN / 64, 256>>>(buf0, W1, b1, buf1);

    // layer 2
    k_spmm_csr<<<(NN + 7) / 8, 256>>>(buf1, buf0);
    k_gemm3<<<NN / 64, 256>>>(buf0, W2, b2, buf1);

    // head
    k_head_naive<<<NN, 64>>>(buf1, Wl, bl, out);
}

// round 11
// speedup vs baseline: 21.9083x; 3.5108x over previous
#include <cuda_runtime.h>
#include <cuda_bf16.h>
#include <cstdint>

// Problem constants (fixed by reference setup_inputs): 40000 nodes, E=640000.
#define NN 40000
#define FF 128
#define CC 40
#define EE 640000

__device__ float g_deg[NN];          // dinv values
__device__ int   g_cnt[NN];          // in-degree (edges only)
__device__ int   g_off[NN];          // CSR row starts (by dst)
__device__ int   g_cur[NN];          // fill cursors
__device__ int   g_csr_src[EE];      // src node per CSR slot
__device__ float g_buf0[NN * FF];
__device__ float g_buf1[NN * FF];
__device__ int   g_is64;

// ---------------------------------------------------------------------------
// Edge dtype detection: int64 little-endian, idx < 2^31 => odd 32-bit words 0.
// ---------------------------------------------------------------------------
__global__ void k_detect(const int* __restrict__ ei) {
    int lane = threadIdx.x;
    int nz = 0;
    for (int i = lane; i < 512; i += 32) nz |= (ei[2 * i + 1] != 0);
    unsigned any = __ballot_sync(0xFFFFFFFFu, nz);
    if (lane == 0) g_is64 = (any == 0u);
}

__device__ __forceinline__ int edge_idx(const int* ei, int pos) {
    if (g_is64) return (int)((const long long*)ei)[pos];
    return ei[pos];
}

// ---------------------------------------------------------------------------
// CSR build
// ---------------------------------------------------------------------------
__global__ void k_cnt_zero() {
    int i = blockIdx.x * blockDim.x + threadIdx.x;
    if (i < NN) g_cnt[i] = 0;
}

__global__ void k_cnt_acc(const int* __restrict__ ei) {
    int i = blockIdx.x * blockDim.x + threadIdx.x;
    if (i < EE) atomicAdd(&g_cnt[edge_idx(ei, EE + i)], 1);   // dst row
}

__global__ void k_dinv() {
    int i = blockIdx.x * blockDim.x + threadIdx.x;
    if (i < NN) g_deg[i] = rsqrtf((float)(g_cnt[i] + 1));     // +1 self loop
}

// Single-pass scan: 1024 threads, 40 elems/thread serial + shuffle scans.
__global__ void k_scan2() {
    __shared__ int wsum[32];
    int tid = threadIdx.x;
    int lane = tid & 31, wid = tid >> 5;
    int base = tid * 40;

    int tot = 0;
    for (int i = 0; i < 40; i++) {
        int idx = base + i;
        if (idx < NN) tot += g_cnt[idx];
    }
    int x = tot;
#pragma unroll
    for (int s = 1; s < 32; s <<= 1) {
        int y = __shfl_up_sync(0xFFFFFFFFu, x, s);
        if (lane >= s) x += y;
    }
    if (lane == 31) wsum[wid] = x;
    __syncthreads();
    if (wid == 0) {
        int w = wsum[lane];
#pragma unroll
        for (int s = 1; s < 32; s <<= 1) {
            int y = __shfl_up_sync(0xFFFFFFFFu, w, s);
            if (lane >= s) w += y;
        }
        wsum[lane] = w;
    }
    __syncthreads();
    int excl = ((wid > 0) ? wsum[wid - 1] : 0) + (x - tot);
    int run = excl;
    for (int i = 0; i < 40; i++) {
        int idx = base + i;
        if (idx < NN) {
            g_off[idx] = run;
            g_cur[idx] = run;
            run += g_cnt[idx];
        }
    }
}

__global__ void k_fill(const int* __restrict__ ei) {
    int e = blockIdx.x * blockDim.x + threadIdx.x;
    if (e >= EE) return;
    int s = edge_idx(ei, e);
    int d = edge_idx(ei, EE + e);
    int pos = atomicAdd(&g_cur[d], 1);
    g_csr_src[pos] = s;
}

// ---------------------------------------------------------------------------
// CSR SpMM with fused self-loop (validated R9): warp per dst row.
// ---------------------------------------------------------------------------
__global__ void k_spmm_csr(const float* __restrict__ X, float* __restrict__ Y) {
    int w = blockIdx.x * 8 + (threadIdx.x >> 5);   // dst node
    if (w >= NN) return;
    int lane = threadIdx.x & 31;

    float dd = g_deg[w];
    float4 acc = ((const float4*)(X + (size_t)w * FF))[lane];
    float sl = dd * dd;
    acc.x *= sl; acc.y *= sl; acc.z *= sl; acc.w *= sl;

    int beg = g_off[w];
    int end = beg + g_cnt[w];
    int j = beg;
    for (; j + 1 < end; j += 2) {
        int s0 = __ldg(&g_csr_src[j]);
        int s1 = __ldg(&g_csr_src[j + 1]);
        float n0 = __ldg(&g_deg[s0]) * dd;
        float n1 = __ldg(&g_deg[s1]) * dd;
        float4 v0 = ((const float4*)(X + (size_t)s0 * FF))[lane];
        float4 v1 = ((const float4*)(X + (size_t)s1 * FF))[lane];
        acc.x = fmaf(v0.x, n0, acc.x); acc.y = fmaf(v0.y, n0, acc.y);
        acc.z = fmaf(v0.z, n0, acc.z); acc.w = fmaf(v0.w, n0, acc.w);
        acc.x = fmaf(v1.x, n1, acc.x); acc.y = fmaf(v1.y, n1, acc.y);
        acc.z = fmaf(v1.z, n1, acc.z); acc.w = fmaf(v1.w, n1, acc.w);
    }
    if (j < end) {
        int s0 = __ldg(&g_csr_src[j]);
        float n0 = __ldg(&g_deg[s0]) * dd;
        float4 v0 = ((const float4*)(X + (size_t)s0 * FF))[lane];
        acc.x = fmaf(v0.x, n0, acc.x); acc.y = fmaf(v0.y, n0, acc.y);
        acc.z = fmaf(v0.z, n0, acc.z); acc.w = fmaf(v0.w, n0, acc.w);
    }

    ((float4*)(Y + (size_t)w * FF))[lane] = acc;
}

// ---------------------------------------------------------------------------
// Tiled GEMM+ReLU (validated R8): Y = relu(X @ W^T + b).
// ---------------------------------------------------------------------------
__global__ void k_gemm3(const float* __restrict__ X,
                        const float* __restrict__ W,
                        const float* __restrict__ b,
                        float* __restrict__ Y) {
    __shared__ float xs[64][33];
    __shared__ float ws[32][132];

    int tid = threadIdx.x;
    int tx = tid & 31;
    int ty = tid >> 5;
    int row0 = blockIdx.x * 64;

    float acc[8][4];
#pragma unroll
    for (int i = 0; i < 8; i++)
#pragma unroll
        for (int j = 0; j < 4; j++) acc[i][j] = 0.0f;

    for (int kb = 0; kb < FF; kb += 32) {
        if (kb) __syncthreads();
#pragma unroll
        for (int u = tid; u < 512; u += 256) {
            int r = u >> 3;
            int c4 = (u & 7) * 4;
            float4 v = *(const float4*)&X[(row0 + r) * FF + kb + c4];
            xs[r][c4 + 0] = v.x; xs[r][c4 + 1] = v.y;
            xs[r][c4 + 2] = v.z; xs[r][c4 + 3] = v.w;
        }
#pragma unroll
        for (int u = tid; u < 1024; u += 256) {
            int f = u >> 3;
            int c4 = (u & 7) * 4;
            float4 v = *(const float4*)&W[f * FF + kb + c4];
            ws[c4 + 0][f] = v.x; ws[c4 + 1][f] = v.y;
            ws[c4 + 2][f] = v.z; ws[c4 + 3][f] = v.w;
        }
        __syncthreads();

#pragma unroll
        for (int k = 0; k < 32; k++) {
            float4 wv = *(const float4*)&ws[k][tx * 4];
            float xv[8];
#pragma unroll
            for (int i = 0; i < 8; i++) xv[i] = xs[ty * 8 + i][k];
#pragma unroll
            for (int i = 0; i < 8; i++) {
                acc[i][0] = fmaf(xv[i], wv.x, acc[i][0]);
                acc[i][1] = fmaf(xv[i], wv.y, acc[i][1]);
                acc[i][2] = fmaf(xv[i], wv.z, acc[i][2]);
                acc[i][3] = fmaf(xv[i], wv.w, acc[i][3]);
            }
        }
    }

    float4 bv = *(const float4*)&b[tx * 4];
#pragma unroll
    for (int i = 0; i < 8; i++) {
        int r = row0 + ty * 8 + i;
        float4 o;
        o.x = fmaxf(acc[i][0] + bv.x, 0.0f);
        o.y = fmaxf(acc[i][1] + bv.y, 0.0f);
        o.z = fmaxf(acc[i][2] + bv.z, 0.0f);
        o.w = fmaxf(acc[i][3] + bv.w, 0.0f);
        *(float4*)&Y[r * FF + tx * 4] = o;
    }
}

// ---------------------------------------------------------------------------
// Tiled head: out = X @ Wl^T + bl.  X: (M,128), Wl: (40,128).
// Grid NN/32, block 256.  Stage X (32x128) + Wl^T (128x40) in smem (39.4KB).
// Thread (ty=tid>>3 -> 1 row, tx=tid&7 -> 5 cols): 1x5 micro-tile.
// ---------------------------------------------------------------------------
__global__ void k_head2(const float* __restrict__ X,
                        const float* __restrict__ W,
                        const float* __restrict__ b,
                        float* __restrict__ Y) {
    __shared__ float xs[32][132];   // [r][k], stride 132 (16B-aligned, 4-bank skew)
    __shared__ float ws[128][44];   // [k][c]

    int tid = threadIdx.x;
    int row0 = blockIdx.x * 32;

    // stage X: 32x128 = 1024 float4s, 4 per thread
#pragma unroll
    for (int u = tid; u < 1024; u += 256) {
        int r = u >> 5;
        int c4 = (u & 31) * 4;
        float4 v = *(const float4*)&X[(row0 + r) * FF + c4];
        xs[r][c4 + 0] = v.x; xs[r][c4 + 1] = v.y;
        xs[r][c4 + 2] = v.z; xs[r][c4 + 3] = v.w;
    }
    // stage W transposed: 40x128 = 1280 float4s, 5 per thread
#pragma unroll
    for (int u = tid; u < 1280; u += 256) {
        int c = u >> 5;
        int k4 = (u & 31) * 4;
        float4 v = *(const float4*)&W[c * FF + k4];
        ws[k4 + 0][c] = v.x; ws[k4 + 1][c] = v.y;
        ws[k4 + 2][c] = v.z; ws[k4 + 3][c] = v.w;
    }
    __syncthreads();

    int tx = tid & 7;      // col group: cols tx*5 .. tx*5+4
    int ty = tid >> 3;     // row: 0..31

    float acc[5] = {0, 0, 0, 0, 0};

#pragma unroll 8
    for (int k = 0; k < FF; k++) {
        float x0 = xs[ty][k];
#pragma unroll
        for (int j = 0; j < 5; j++)
            acc[j] = fmaf(x0, ws[k][tx * 5 + j], acc[j]);
    }

    int r = row0 + ty;
#pragma unroll
    for (int j = 0; j < 5; j++) {
        int c = tx * 5 + j;
        Y[r * CC + c] = acc[j] + b[c];
    }
}

// ---------------------------------------------------------------------------
// Launch
// ---------------------------------------------------------------------------
extern "C" void kernel_launch(void* const* d_in, const int* in_sizes, int n_in,
                              void* d_out, int out_size) {
    const float* x   = (const float*)d_in[0];
    const int*   ei  = (const int*)d_in[1];
    const float* W1  = (const float*)d_in[2];
    const float* b1  = (const float*)d_in[3];
    const float* W2  = (const float*)d_in[4];
    const float* b2  = (const float*)d_in[5];
    const float* Wl  = (const float*)d_in[6];
    const float* bl  = (const float*)d_in[7];
    float*       out = (float*)d_out;

    float* buf0; cudaGetSymbolAddress((void**)&buf0, g_buf0);
    float* buf1; cudaGetSymbolAddress((void**)&buf1, g_buf1);

    k_detect<<<1, 32>>>(ei);

    // CSR build (by dst) + dinv
    k_cnt_zero<<<(NN + 255) / 256, 256>>>();
    k_cnt_acc<<<(EE + 255) / 256, 256>>>(ei);
    k_dinv<<<(NN + 255) / 256, 256>>>();
    k_scan2<<<1, 1024>>>();
    k_fill<<<(EE + 255) / 256, 256>>>(ei);

    // layer 1
    k_spmm_csr<<<(NN + 7) / 8, 256>>>(x, buf0);
    k_gemm3<<<NN / 64, 256>>>(buf0, W1, b1, buf1);

    // layer 2
    k_spmm_csr<<<(NN + 7) / 8, 256>>>(buf1, buf0);
    k_gemm3<<<NN / 64, 256>>>(buf0, W2, b2, buf1);

    // head
    k_head2<<<NN / 32, 256>>>(buf1, Wl, bl, out);
}